// round 9
// baseline (speedup 1.0000x reference)
#include <cuda_runtime.h>
#include <cuda_bf16.h>

// SpatialTransformer: B=16, H=W=384, C=32, fp32, NHWC.
// R5 winner shape, setup fused inline (single kernel, no setup launch).
// 1D grid, row-major block order. Block = 64-pixel row segment.
// 8 threads/pixel (one float4 each); each thread handles TWO pixels
// (j, j+32) -> 8 front-batched coalesced LDG.128. Plain STG.128 stores.

#define B_ 16
#define H_ 384
#define W_ 384
#define C_ 32
#define CV_ (C_/4)   // float4 groups per pixel = 8

struct Tap {
    int ia, ib, ic, id;
    float wa, wb, wc, wd;
};

__device__ __forceinline__ Tap make_tap(int j, float ys,
                                        float m00, float m01, float cy,
                                        float m10, float m11, float cx,
                                        int base, int cg)
{
    const float STEP = 2.0f / 383.0f;
    float xs = __fadd_rn(__fmul_rn((float)j, STEP), -1.0f);

    float gx = __fadd_rn(__fmaf_rn(m01, ys, __fmul_rn(m00, xs)), cy);
    float gy = __fadd_rn(__fmaf_rn(m11, ys, __fmul_rn(m10, xs)), cx);

    float x = __fmul_rn(__fmul_rn(__fadd_rn(gx, 1.0f), 384.0f), 0.5f);
    float y = __fmul_rn(__fmul_rn(__fadd_rn(gy, 1.0f), 384.0f), 0.5f);

    int x0 = (int)floorf(x);
    int y0 = (int)floorf(y);
    int x1 = x0 + 1;
    int y1 = y0 + 1;
    x0 = min(max(x0, 0), W_ - 1);
    x1 = min(max(x1, 0), W_ - 1);
    y0 = min(max(y0, 0), H_ - 1);
    y1 = min(max(y1, 0), H_ - 1);
    float x0f = (float)x0, x1f = (float)x1;
    float y0f = (float)y0, y1f = (float)y1;

    float wxa = __fsub_rn(x1f, x);
    float wxc = __fsub_rn(x, x0f);
    float wya = __fsub_rn(y1f, y);
    float wyb = __fsub_rn(y, y0f);

    Tap t;
    t.wa = __fmul_rn(wxa, wya);
    t.wb = __fmul_rn(wxa, wyb);
    t.wc = __fmul_rn(wxc, wya);
    t.wd = __fmul_rn(wxc, wyb);
    t.ia = base + (y0 * W_ + x0) * CV_ + cg;
    t.ib = base + (y1 * W_ + x0) * CV_ + cg;
    t.ic = base + (y0 * W_ + x1) * CV_ + cg;
    t.id = base + (y1 * W_ + x1) * CV_ + cg;
    return t;
}

// blocks: B*H*(W/64) = 16*384*6 = 36864, row-major (batch, row, tile)
__global__ __launch_bounds__(256)
void st_bilinear_kernel(const float4* __restrict__ img,
                        const float*  __restrict__ theta,
                        float4* __restrict__ out)
{
    const int tid = threadIdx.x;
    const int blk = blockIdx.x;

    const int tile = blk % 6;                 // 64-px column tile
    const int bi   = blk / 6;                 // b*384 + i
    const int i    = bi % H_;
    const int b    = bi / H_;

    const int j0 = tile * 64 + (tid >> 3);    // first pixel column
    const int j1 = j0 + 32;                   // second pixel column
    const int cg = tid & 7;                   // float4 channel group

    // ---- inline per-batch theta adjustment (jnp.linalg.inv, sgetrf+strsm) ----
    // b is CTA-uniform; ~50 extra instrs of independent ALU work, runs in
    // issue slack of the memory pipeline. Identical IEEE op sequence to the
    // previous setup kernel -> bit-identical coefficients.
    const float* t = theta + b * 6;
    float a00 = __ldg(t + 0), a01 = __ldg(t + 1), a02 = __ldg(t + 2);
    float a10 = __ldg(t + 3), a11 = __ldg(t + 4), a12 = __ldg(t + 5);

    bool piv = fabsf(a10) > fabsf(a00);
    float b00 = piv ? a10 : a00;
    float b01 = piv ? a11 : a01;
    float b10 = piv ? a00 : a10;
    float b11 = piv ? a01 : a11;

    float rr  = __frcp_rn(b00);
    float l   = __fmul_rn(b10, rr);
    float u11 = __fsub_rn(b11, __fmul_rn(l, b01));

    float x10 = __fdiv_rn(-l, u11);
    float x00 = __fdiv_rn(__fsub_rn(1.0f, __fmul_rn(x10, b01)), b00);
    float x11 = __fdiv_rn(1.0f, u11);
    float x01 = __fdiv_rn(-__fmul_rn(x11, b01), b00);

    float m00 = piv ? x01 : x00;
    float m01 = piv ? x00 : x01;
    float m10 = piv ? x11 : x10;
    float m11 = piv ? x10 : x11;

    float xc = __fmul_rn(__fadd_rn(-a02, 0.5f), m00);
    float yc = __fmul_rn(__fadd_rn(-a12, 0.5f), m11);
    float cy = __fsub_rn(__fmul_rn(yc, 2.0f), 1.0f);
    float cx = __fsub_rn(__fmul_rn(xc, 2.0f), 1.0f);

    const float STEP = 2.0f / 383.0f;
    float ys = __fadd_rn(__fmul_rn((float)i, STEP), -1.0f);

    const int base = b * (H_ * W_ * CV_);

    Tap t0 = make_tap(j0, ys, m00, m01, cy, m10, m11, cx, base, cg);
    Tap t1 = make_tap(j1, ys, m00, m01, cy, m10, m11, cx, base, cg);

    // 8 front-batched, fully-coalesced LDG.128 (4 pixels/warp per tap)
    float4 a0 = __ldg(img + t0.ia);
    float4 b0 = __ldg(img + t0.ib);
    float4 c0 = __ldg(img + t0.ic);
    float4 d0 = __ldg(img + t0.id);
    float4 a1 = __ldg(img + t1.ia);
    float4 b1 = __ldg(img + t1.ib);
    float4 c1 = __ldg(img + t1.ic);
    float4 d1 = __ldg(img + t1.id);

#define BLEND(T,A,B,C,D,f) \
    __fadd_rn(__fadd_rn(__fadd_rn(__fmul_rn((T).wa, (A).f), __fmul_rn((T).wb, (B).f)), \
                         __fmul_rn((T).wc, (C).f)), __fmul_rn((T).wd, (D).f))

    float4 r0, r1;
    r0.x = BLEND(t0, a0, b0, c0, d0, x);
    r0.y = BLEND(t0, a0, b0, c0, d0, y);
    r0.z = BLEND(t0, a0, b0, c0, d0, z);
    r0.w = BLEND(t0, a0, b0, c0, d0, w);
    r1.x = BLEND(t1, a1, b1, c1, d1, x);
    r1.y = BLEND(t1, a1, b1, c1, d1, y);
    r1.z = BLEND(t1, a1, b1, c1, d1, z);
    r1.w = BLEND(t1, a1, b1, c1, d1, w);
#undef BLEND

    const int orow = base + (i * W_) * CV_ + cg;
    out[orow + j0 * CV_] = r0;     // plain cached stores
    out[orow + j1 * CV_] = r1;
}

extern "C" void kernel_launch(void* const* d_in, const int* in_sizes, int n_in,
                              void* d_out, int out_size)
{
    const float4* img   = (const float4*)d_in[0];   // images: (16,384,384,32) f32
    const float*  theta = (const float*)d_in[1];    // theta:  (16,6) f32
    float4* out = (float4*)d_out;

    const int blocks = B_ * H_ * (W_ / 64);   // 36864
    st_bilinear_kernel<<<blocks, 256>>>(img, theta, out);
}

// round 10
// speedup vs baseline: 1.1274x; 1.1274x over previous
#include <cuda_runtime.h>
#include <cuda_bf16.h>

// SpatialTransformer: B=16, H=W=384, C=32, fp32, NHWC.
// R5 winner body + per-CTA setup: thread 0 computes the 6 batch coefficients
// into smem (div slow-path runs once per CTA, not per thread), barrier,
// broadcast read. Single kernel -> no setup launch overhead.
// 1D grid, row-major block order. Block = 64-pixel row segment.
// 8 threads/pixel; each thread handles TWO pixels (j, j+32).

#define B_ 16
#define H_ 384
#define W_ 384
#define C_ 32
#define CV_ (C_/4)   // float4 groups per pixel = 8

struct Tap {
    int ia, ib, ic, id;
    float wa, wb, wc, wd;
};

__device__ __forceinline__ Tap make_tap(int j, float ys,
                                        float m00, float m01, float cy,
                                        float m10, float m11, float cx,
                                        int base, int cg)
{
    const float STEP = 2.0f / 383.0f;
    float xs = __fadd_rn(__fmul_rn((float)j, STEP), -1.0f);

    float gx = __fadd_rn(__fmaf_rn(m01, ys, __fmul_rn(m00, xs)), cy);
    float gy = __fadd_rn(__fmaf_rn(m11, ys, __fmul_rn(m10, xs)), cx);

    float x = __fmul_rn(__fmul_rn(__fadd_rn(gx, 1.0f), 384.0f), 0.5f);
    float y = __fmul_rn(__fmul_rn(__fadd_rn(gy, 1.0f), 384.0f), 0.5f);

    int x0 = (int)floorf(x);
    int y0 = (int)floorf(y);
    int x1 = x0 + 1;
    int y1 = y0 + 1;
    x0 = min(max(x0, 0), W_ - 1);
    x1 = min(max(x1, 0), W_ - 1);
    y0 = min(max(y0, 0), H_ - 1);
    y1 = min(max(y1, 0), H_ - 1);
    float x0f = (float)x0, x1f = (float)x1;
    float y0f = (float)y0, y1f = (float)y1;

    float wxa = __fsub_rn(x1f, x);
    float wxc = __fsub_rn(x, x0f);
    float wya = __fsub_rn(y1f, y);
    float wyb = __fsub_rn(y, y0f);

    Tap t;
    t.wa = __fmul_rn(wxa, wya);
    t.wb = __fmul_rn(wxa, wyb);
    t.wc = __fmul_rn(wxc, wya);
    t.wd = __fmul_rn(wxc, wyb);
    t.ia = base + (y0 * W_ + x0) * CV_ + cg;
    t.ib = base + (y1 * W_ + x0) * CV_ + cg;
    t.ic = base + (y0 * W_ + x1) * CV_ + cg;
    t.id = base + (y1 * W_ + x1) * CV_ + cg;
    return t;
}

// blocks: B*H*(W/64) = 16*384*6 = 36864, row-major (batch, row, tile)
__global__ __launch_bounds__(256)
void st_bilinear_kernel(const float4* __restrict__ img,
                        const float*  __restrict__ theta,
                        float4* __restrict__ out)
{
    __shared__ float scoef[6];

    const int tid = threadIdx.x;
    const int blk = blockIdx.x;

    const int tile = blk % 6;                 // 64-px column tile
    const int bi   = blk / 6;                 // b*384 + i
    const int i    = bi % H_;
    const int b    = bi / H_;

    // ---- per-CTA theta adjustment (thread 0 only; identical IEEE sequence) ----
    if (tid == 0) {
        const float* t = theta + b * 6;
        float a00 = __ldg(t + 0), a01 = __ldg(t + 1), a02 = __ldg(t + 2);
        float a10 = __ldg(t + 3), a11 = __ldg(t + 4), a12 = __ldg(t + 5);

        bool piv = fabsf(a10) > fabsf(a00);
        float b00 = piv ? a10 : a00;
        float b01 = piv ? a11 : a01;
        float b10 = piv ? a00 : a10;
        float b11 = piv ? a01 : a11;

        float rr  = __frcp_rn(b00);
        float l   = __fmul_rn(b10, rr);
        float u11 = __fsub_rn(b11, __fmul_rn(l, b01));

        float x10 = __fdiv_rn(-l, u11);
        float x00 = __fdiv_rn(__fsub_rn(1.0f, __fmul_rn(x10, b01)), b00);
        float x11 = __fdiv_rn(1.0f, u11);
        float x01 = __fdiv_rn(-__fmul_rn(x11, b01), b00);

        float m00 = piv ? x01 : x00;
        float m01 = piv ? x00 : x01;
        float m10 = piv ? x11 : x10;
        float m11 = piv ? x10 : x11;

        float xc = __fmul_rn(__fadd_rn(-a02, 0.5f), m00);
        float yc = __fmul_rn(__fadd_rn(-a12, 0.5f), m11);
        scoef[0] = m00;
        scoef[1] = m01;
        scoef[2] = __fsub_rn(__fmul_rn(yc, 2.0f), 1.0f);   // cy
        scoef[3] = m10;
        scoef[4] = m11;
        scoef[5] = __fsub_rn(__fmul_rn(xc, 2.0f), 1.0f);   // cx
    }
    __syncthreads();

    const int j0 = tile * 64 + (tid >> 3);    // first pixel column
    const int j1 = j0 + 32;                   // second pixel column
    const int cg = tid & 7;                   // float4 channel group

    float m00 = scoef[0], m01 = scoef[1], cy = scoef[2];
    float m10 = scoef[3], m11 = scoef[4], cx = scoef[5];

    const float STEP = 2.0f / 383.0f;
    float ys = __fadd_rn(__fmul_rn((float)i, STEP), -1.0f);

    const int base = b * (H_ * W_ * CV_);

    Tap t0 = make_tap(j0, ys, m00, m01, cy, m10, m11, cx, base, cg);
    Tap t1 = make_tap(j1, ys, m00, m01, cy, m10, m11, cx, base, cg);

    // 8 front-batched, fully-coalesced LDG.128 (4 pixels/warp per tap)
    float4 a0 = __ldg(img + t0.ia);
    float4 b0 = __ldg(img + t0.ib);
    float4 c0 = __ldg(img + t0.ic);
    float4 d0 = __ldg(img + t0.id);
    float4 a1 = __ldg(img + t1.ia);
    float4 b1 = __ldg(img + t1.ib);
    float4 c1 = __ldg(img + t1.ic);
    float4 d1 = __ldg(img + t1.id);

#define BLEND(T,A,B,C,D,f) \
    __fadd_rn(__fadd_rn(__fadd_rn(__fmul_rn((T).wa, (A).f), __fmul_rn((T).wb, (B).f)), \
                         __fmul_rn((T).wc, (C).f)), __fmul_rn((T).wd, (D).f))

    float4 r0, r1;
    r0.x = BLEND(t0, a0, b0, c0, d0, x);
    r0.y = BLEND(t0, a0, b0, c0, d0, y);
    r0.z = BLEND(t0, a0, b0, c0, d0, z);
    r0.w = BLEND(t0, a0, b0, c0, d0, w);
    r1.x = BLEND(t1, a1, b1, c1, d1, x);
    r1.y = BLEND(t1, a1, b1, c1, d1, y);
    r1.z = BLEND(t1, a1, b1, c1, d1, z);
    r1.w = BLEND(t1, a1, b1, c1, d1, w);
#undef BLEND

    const int orow = base + (i * W_) * CV_ + cg;
    out[orow + j0 * CV_] = r0;     // plain cached stores
    out[orow + j1 * CV_] = r1;
}

extern "C" void kernel_launch(void* const* d_in, const int* in_sizes, int n_in,
                              void* d_out, int out_size)
{
    const float4* img   = (const float4*)d_in[0];   // images: (16,384,384,32) f32
    const float*  theta = (const float*)d_in[1];    // theta:  (16,6) f32
    float4* out = (float4*)d_out;

    const int blocks = B_ * H_ * (W_ / 64);   // 36864
    st_bilinear_kernel<<<blocks, 256>>>(img, theta, out);
}